// round 10
// baseline (speedup 1.0000x reference)
#include <cuda_runtime.h>
#include <cuda_fp16.h>

#define MAX_NODES  75008
#define MAX_EDGES  1200128
#define F  64
#define F4 (F / 4)
#define SCAN_B 1024
#define MAX_SCAN_BLOCKS 256

// __device__ scratch (allocation-free rule)
__device__ int   g_offset[MAX_NODES];       // CSR start per node
__device__ int   g_cursor[MAX_NODES];       // atomic fill cursor
__device__ float g_inv[MAX_NODES];          // rsqrt(degree)
__device__ int   g_blocksum[MAX_SCAN_BLOCKS];
__device__ int   g_sorted[MAX_EDGES];       // src ids bucketed by dst
__device__ uint4 g_P[MAX_NODES * 8];        // fp16 messages: 8 x uint4 = 64 halves/row
__device__ float g_agg[MAX_NODES * F];

__device__ __forceinline__ int node_count(const float* degree, int i, int N) {
    return (i < N) ? (__float2int_rn(degree[i]) - 1) : 0;   // degree = indeg+1
}

__device__ __forceinline__ int warp_incl_scan(int v) {
    #pragma unroll
    for (int o = 1; o < 32; o <<= 1) {
        int u = __shfl_up_sync(0xffffffffu, v, o);
        if ((threadIdx.x & 31) >= o) v += u;
    }
    return v;
}

__global__ void scan1_kernel(const float* __restrict__ degree, int N) {
    int i = blockIdx.x * SCAN_B + threadIdx.x;
    int c = node_count(degree, i, N);
    int w = __reduce_add_sync(0xffffffffu, c);
    __shared__ int ws[32];
    if ((threadIdx.x & 31) == 0) ws[threadIdx.x >> 5] = w;
    __syncthreads();
    if (threadIdx.x < 32) {
        int v = (threadIdx.x < (SCAN_B / 32)) ? ws[threadIdx.x] : 0;
        v = __reduce_add_sync(0xffffffffu, v);
        if (threadIdx.x == 0) g_blocksum[blockIdx.x] = v;
    }
}

__global__ void scan2_kernel(int nb) {
    __shared__ int s[MAX_SCAN_BLOCKS];
    int tid = threadIdx.x;
    int v = (tid < nb) ? g_blocksum[tid] : 0;
    s[tid] = v;
    __syncthreads();
    #pragma unroll
    for (int o = 1; o < MAX_SCAN_BLOCKS; o <<= 1) {
        int u = (tid >= o) ? s[tid - o] : 0;
        __syncthreads();
        s[tid] += u;
        __syncthreads();
    }
    if (tid < nb) g_blocksum[tid] = s[tid] - v;   // exclusive
}

__global__ void scan3_kernel(const float* __restrict__ degree, int N) {
    int tid = threadIdx.x;
    int i = blockIdx.x * SCAN_B + tid;
    int c = node_count(degree, i, N);

    int lane = tid & 31, wid = tid >> 5;
    int incl = warp_incl_scan(c);
    __shared__ int ws[32];
    if (lane == 31) ws[wid] = incl;
    __syncthreads();
    if (wid == 0) {
        int v = (lane < (SCAN_B / 32)) ? ws[lane] : 0;
        v = warp_incl_scan(v);
        ws[lane] = v;
    }
    __syncthreads();
    int base = (wid ? ws[wid - 1] : 0) + g_blocksum[blockIdx.x];
    int excl = base + incl - c;
    if (i < N) {
        g_offset[i] = excl;
        g_cursor[i] = excl;
        g_inv[i]    = rsqrtf(degree[i]);
    }
}

// FUSED bucket + prescale (R8/R9: 22us vs 26.5 split — keep).
__global__ void bucket_prescale_kernel(const float* __restrict__ feature,
                                       const float* __restrict__ degree,
                                       const int*   __restrict__ src,
                                       const int*   __restrict__ dst,
                                       int E, int N) {
    int t = blockIdx.x * blockDim.x + threadIdx.x;

    if (t < N * 8) {          // prescale: P[n] = fp16(feature[n]*rsqrt(deg[n]))
        int node = t >> 3;
        int c = t & 7;
        float s = rsqrtf(__ldg(degree + node));
        const float4* frow =
            reinterpret_cast<const float4*>(feature) + node * F4 + c * 2;
        float4 a = __ldg(frow);
        float4 b = __ldg(frow + 1);

        __half2 h0 = __floats2half2_rn(a.x * s, a.y * s);
        __half2 h1 = __floats2half2_rn(a.z * s, a.w * s);
        __half2 h2 = __floats2half2_rn(b.x * s, b.y * s);
        __half2 h3 = __floats2half2_rn(b.z * s, b.w * s);

        uint4 p;
        p.x = *reinterpret_cast<unsigned*>(&h0);
        p.y = *reinterpret_cast<unsigned*>(&h1);
        p.z = *reinterpret_cast<unsigned*>(&h2);
        p.w = *reinterpret_cast<unsigned*>(&h3);
        g_P[node * 8 + c] = p;
    }

    if (t < E) {              // bucket: scalar per-edge
        int d = __ldg(dst + t);
        int pos = atomicAdd(&g_cursor[d], 1);
        g_sorted[pos] = __ldg(src + t);
    }
}

// gather v3: 8 lanes/node. Indices fetched in COALESCED batches of 8
// (lane c loads start+base+c), distributed by shfl(width=8); then 8
// INDEPENDENT 128B row loads issue back-to-back per group.
// Per warp: 4 groups x 8 = 32 rows in flight. fp32 accumulation.
// NOTE: N*8 = 600000 is a multiple of 32 -> every active warp is fully
// active, so full-mask shfl after the early-exit is safe.
__global__ void __launch_bounds__(256)
gather_kernel(const float* __restrict__ degree, int N) {
    int t = blockIdx.x * blockDim.x + threadIdx.x;
    int node = t >> 3;
    int c = t & 7;
    if (node >= N) return;

    int start = g_offset[node];
    int cnt = __float2int_rn(__ldg(degree + node)) - 1;

    float acc[8] = {0.f, 0.f, 0.f, 0.f, 0.f, 0.f, 0.f, 0.f};

    for (int base = 0; base < cnt; base += 8) {
        int i = base + c;
        int idx = (i < cnt) ? __ldg(g_sorted + start + i) : -1;   // coalesced

        #pragma unroll
        for (int j = 0; j < 8; j++) {
            int s = __shfl_sync(0xffffffffu, idx, j, 8);
            if (s >= 0) {
                uint4 p = g_P[s * 8 + c];
                __half2 h0 = *reinterpret_cast<__half2*>(&p.x);
                __half2 h1 = *reinterpret_cast<__half2*>(&p.y);
                __half2 h2 = *reinterpret_cast<__half2*>(&p.z);
                __half2 h3 = *reinterpret_cast<__half2*>(&p.w);
                float2 f0 = __half22float2(h0);
                float2 f1 = __half22float2(h1);
                float2 f2 = __half22float2(h2);
                float2 f3 = __half22float2(h3);
                acc[0] += f0.x; acc[1] += f0.y;
                acc[2] += f1.x; acc[3] += f1.y;
                acc[4] += f2.x; acc[5] += f2.y;
                acc[6] += f3.x; acc[7] += f3.y;
            }
        }
    }

    float4* orow = reinterpret_cast<float4*>(g_agg + node * F + c * 8);
    orow[0] = make_float4(acc[0], acc[1], acc[2], acc[3]);
    orow[1] = make_float4(acc[4], acc[5], acc[6], acc[7]);
}

// node apply with PACKED f32x2 FFMA (PTX-only FFMA2, 2x FMA lanes).
__global__ void __launch_bounds__(256)
gemm_kernel(const float* __restrict__ W,
            const float* __restrict__ b,
            float* __restrict__ out, int N) {
    __shared__ float4 Ws[F * F4];     // W[k][j4]
    __shared__ float4 bs[F4];

    for (int i = threadIdx.x; i < F * F4; i += blockDim.x)
        Ws[i] = reinterpret_cast<const float4*>(W)[i];
    if (threadIdx.x < F4)
        bs[threadIdx.x] = reinterpret_cast<const float4*>(b)[threadIdx.x];
    __syncthreads();

    int row = blockIdx.x * blockDim.x + threadIdx.x;
    if (row >= N) return;

    unsigned long long acc[F / 2];
    #pragma unroll
    for (int j = 0; j < F4; j++) {
        float4 bb = bs[j];
        asm("mov.b64 %0, {%1, %2};" : "=l"(acc[2 * j + 0]) : "f"(bb.x), "f"(bb.y));
        asm("mov.b64 %0, {%1, %2};" : "=l"(acc[2 * j + 1]) : "f"(bb.z), "f"(bb.w));
    }

    float s = g_inv[row];
    const float4* arow = reinterpret_cast<const float4*>(g_agg + (long)row * F);

    #pragma unroll 4
    for (int k4 = 0; k4 < F4; k4++) {
        float4 hv = __ldg(arow + k4);
        hv.x *= s; hv.y *= s; hv.z *= s; hv.w *= s;
        #pragma unroll
        for (int kk = 0; kk < 4; kk++) {
            float h = (kk == 0) ? hv.x : (kk == 1) ? hv.y : (kk == 2) ? hv.z : hv.w;
            unsigned long long h2;
            asm("mov.b64 %0, {%1, %1};" : "=l"(h2) : "f"(h));   // (h, h)
            int k = k4 * 4 + kk;
            #pragma unroll
            for (int j = 0; j < F4; j++) {
                float4 w = Ws[k * F4 + j];       // warp-uniform smem broadcast
                unsigned long long w01, w23;
                asm("mov.b64 %0, {%1, %2};" : "=l"(w01) : "f"(w.x), "f"(w.y));
                asm("mov.b64 %0, {%1, %2};" : "=l"(w23) : "f"(w.z), "f"(w.w));
                asm("fma.rn.f32x2 %0, %1, %2, %0;"
                    : "+l"(acc[2 * j + 0]) : "l"(h2), "l"(w01));
                asm("fma.rn.f32x2 %0, %1, %2, %0;"
                    : "+l"(acc[2 * j + 1]) : "l"(h2), "l"(w23));
            }
        }
    }

    float4* orow = reinterpret_cast<float4*>(out + (long)row * F);
    #pragma unroll
    for (int j = 0; j < F4; j++) {
        float x, y, z, w;
        asm("mov.b64 {%0, %1}, %2;" : "=f"(x), "=f"(y) : "l"(acc[2 * j + 0]));
        asm("mov.b64 {%0, %1}, %2;" : "=f"(z), "=f"(w) : "l"(acc[2 * j + 1]));
        orow[j] = make_float4(x, y, z, w);
    }
}

// ---------------------------------------------------------------------------
extern "C" void kernel_launch(void* const* d_in, const int* in_sizes, int n_in,
                              void* d_out, int out_size) {
    const float* feature = (const float*)d_in[0];
    const float* degree  = (const float*)d_in[1];
    const int*   src     = (const int*)d_in[2];
    const int*   dst     = (const int*)d_in[3];
    const float* W       = (const float*)d_in[4];
    const float* b       = (const float*)d_in[5];
    float*       out     = (float*)d_out;

    int N = in_sizes[1];
    int E = in_sizes[2];
    int nb = (N + SCAN_B - 1) / SCAN_B;

    scan1_kernel<<<nb, SCAN_B>>>(degree, N);
    scan2_kernel<<<1, MAX_SCAN_BLOCKS>>>(nb);
    scan3_kernel<<<nb, SCAN_B>>>(degree, N);

    int fthreads = (E > N * 8) ? E : N * 8;
    bucket_prescale_kernel<<<(fthreads + 255) / 256, 256>>>(
        feature, degree, src, dst, E, N);

    int gthreads = N * 8;
    gather_kernel<<<(gthreads + 255) / 256, 256>>>(degree, N);

    gemm_kernel<<<(N + 255) / 256, 256>>>(W, b, out, N);
}

// round 11
// speedup vs baseline: 1.0059x; 1.0059x over previous
#include <cuda_runtime.h>
#include <cuda_fp16.h>

#define MAX_NODES  75008
#define MAX_EDGES  1200128
#define F  64
#define F4 (F / 4)
#define SCAN_B 1024
#define MAX_SCAN_BLOCKS 256

// __device__ scratch (allocation-free rule)
__device__ int   g_offset[MAX_NODES];       // CSR start per node
__device__ int   g_cursor[MAX_NODES];       // atomic fill cursor
__device__ float g_inv[MAX_NODES];          // rsqrt(degree)
__device__ int   g_blocksum[MAX_SCAN_BLOCKS];
__device__ int   g_sorted[MAX_EDGES];       // src ids bucketed by dst
__device__ uint4 g_P[MAX_NODES * 8];        // fp16 messages: 8 x uint4 = 64 halves/row
__device__ float g_agg[MAX_NODES * F];

__device__ __forceinline__ int node_count(const float* degree, int i, int N) {
    return (i < N) ? (__float2int_rn(degree[i]) - 1) : 0;   // degree = indeg+1
}

__device__ __forceinline__ int warp_incl_scan(int v) {
    #pragma unroll
    for (int o = 1; o < 32; o <<= 1) {
        int u = __shfl_up_sync(0xffffffffu, v, o);
        if ((threadIdx.x & 31) >= o) v += u;
    }
    return v;
}

__global__ void scan1_kernel(const float* __restrict__ degree, int N) {
    int i = blockIdx.x * SCAN_B + threadIdx.x;
    int c = node_count(degree, i, N);
    int w = __reduce_add_sync(0xffffffffu, c);
    __shared__ int ws[32];
    if ((threadIdx.x & 31) == 0) ws[threadIdx.x >> 5] = w;
    __syncthreads();
    if (threadIdx.x < 32) {
        int v = (threadIdx.x < (SCAN_B / 32)) ? ws[threadIdx.x] : 0;
        v = __reduce_add_sync(0xffffffffu, v);
        if (threadIdx.x == 0) g_blocksum[blockIdx.x] = v;
    }
}

__global__ void scan2_kernel(int nb) {
    __shared__ int s[MAX_SCAN_BLOCKS];
    int tid = threadIdx.x;
    int v = (tid < nb) ? g_blocksum[tid] : 0;
    s[tid] = v;
    __syncthreads();
    #pragma unroll
    for (int o = 1; o < MAX_SCAN_BLOCKS; o <<= 1) {
        int u = (tid >= o) ? s[tid - o] : 0;
        __syncthreads();
        s[tid] += u;
        __syncthreads();
    }
    if (tid < nb) g_blocksum[tid] = s[tid] - v;   // exclusive
}

__global__ void scan3_kernel(const float* __restrict__ degree, int N) {
    int tid = threadIdx.x;
    int i = blockIdx.x * SCAN_B + tid;
    int c = node_count(degree, i, N);

    int lane = tid & 31, wid = tid >> 5;
    int incl = warp_incl_scan(c);
    __shared__ int ws[32];
    if (lane == 31) ws[wid] = incl;
    __syncthreads();
    if (wid == 0) {
        int v = (lane < (SCAN_B / 32)) ? ws[lane] : 0;
        v = warp_incl_scan(v);
        ws[lane] = v;
    }
    __syncthreads();
    int base = (wid ? ws[wid - 1] : 0) + g_blocksum[blockIdx.x];
    int excl = base + incl - c;
    if (i < N) {
        g_offset[i] = excl;
        g_cursor[i] = excl;
        g_inv[i]    = rsqrtf(degree[i]);
    }
}

// FUSED bucket + prescale (stable at ~22us across R8-R10 — keep).
__global__ void bucket_prescale_kernel(const float* __restrict__ feature,
                                       const float* __restrict__ degree,
                                       const int*   __restrict__ src,
                                       const int*   __restrict__ dst,
                                       int E, int N) {
    int t = blockIdx.x * blockDim.x + threadIdx.x;

    if (t < N * 8) {          // prescale: P[n] = fp16(feature[n]*rsqrt(deg[n]))
        int node = t >> 3;
        int c = t & 7;
        float s = rsqrtf(__ldg(degree + node));
        const float4* frow =
            reinterpret_cast<const float4*>(feature) + node * F4 + c * 2;
        float4 a = __ldg(frow);
        float4 b = __ldg(frow + 1);

        __half2 h0 = __floats2half2_rn(a.x * s, a.y * s);
        __half2 h1 = __floats2half2_rn(a.z * s, a.w * s);
        __half2 h2 = __floats2half2_rn(b.x * s, b.y * s);
        __half2 h3 = __floats2half2_rn(b.z * s, b.w * s);

        uint4 p;
        p.x = *reinterpret_cast<unsigned*>(&h0);
        p.y = *reinterpret_cast<unsigned*>(&h1);
        p.z = *reinterpret_cast<unsigned*>(&h2);
        p.w = *reinterpret_cast<unsigned*>(&h3);
        g_P[node * 8 + c] = p;
    }

    if (t < E) {              // bucket: scalar per-edge
        int d = __ldg(dst + t);
        int pos = atomicAdd(&g_cursor[d], 1);
        g_sorted[pos] = __ldg(src + t);
    }
}

// gather v4: 2 NODES PER WARP (16 lanes/node, lane owns 8B = 4 halves).
// Divergence waste drops from max-of-4 Poisson (~30%) to max-of-2 (~14%);
// unroll 8 keeps 2 streams x 8 = 16 independent row loads per warp.
// Row read = 16 lanes x 8B = 128B coalesced. fp32 accumulation.
__global__ void __launch_bounds__(256)
gather_kernel(const float* __restrict__ degree, int N) {
    int t = blockIdx.x * blockDim.x + threadIdx.x;
    int node = t >> 4;
    int c = t & 15;           // 8B chunk within the 128B fp16 row
    if (node >= N) return;

    int start = g_offset[node];
    int cnt = __float2int_rn(__ldg(degree + node)) - 1;

    float acc0 = 0.f, acc1 = 0.f, acc2 = 0.f, acc3 = 0.f;
    const uint2* P2 = reinterpret_cast<const uint2*>(g_P);   // row = 16 uint2

    #pragma unroll 8
    for (int i = 0; i < cnt; i++) {
        int s = __ldg(g_sorted + start + i);     // broadcast across 16 lanes
        uint2 p = __ldg(P2 + s * 16 + c);
        __half2 h0 = *reinterpret_cast<__half2*>(&p.x);
        __half2 h1 = *reinterpret_cast<__half2*>(&p.y);
        float2 f0 = __half22float2(h0);
        float2 f1 = __half22float2(h1);
        acc0 += f0.x; acc1 += f0.y;
        acc2 += f1.x; acc3 += f1.y;
    }

    reinterpret_cast<float4*>(g_agg + node * F)[c] =
        make_float4(acc0, acc1, acc2, acc3);
}

// node apply with PACKED f32x2 FFMA (PTX-only FFMA2, 2x FMA lanes).
__global__ void __launch_bounds__(256)
gemm_kernel(const float* __restrict__ W,
            const float* __restrict__ b,
            float* __restrict__ out, int N) {
    __shared__ float4 Ws[F * F4];     // W[k][j4]
    __shared__ float4 bs[F4];

    for (int i = threadIdx.x; i < F * F4; i += blockDim.x)
        Ws[i] = reinterpret_cast<const float4*>(W)[i];
    if (threadIdx.x < F4)
        bs[threadIdx.x] = reinterpret_cast<const float4*>(b)[threadIdx.x];
    __syncthreads();

    int row = blockIdx.x * blockDim.x + threadIdx.x;
    if (row >= N) return;

    unsigned long long acc[F / 2];
    #pragma unroll
    for (int j = 0; j < F4; j++) {
        float4 bb = bs[j];
        asm("mov.b64 %0, {%1, %2};" : "=l"(acc[2 * j + 0]) : "f"(bb.x), "f"(bb.y));
        asm("mov.b64 %0, {%1, %2};" : "=l"(acc[2 * j + 1]) : "f"(bb.z), "f"(bb.w));
    }

    float s = g_inv[row];
    const float4* arow = reinterpret_cast<const float4*>(g_agg + (long)row * F);

    #pragma unroll 4
    for (int k4 = 0; k4 < F4; k4++) {
        float4 hv = __ldg(arow + k4);
        hv.x *= s; hv.y *= s; hv.z *= s; hv.w *= s;
        #pragma unroll
        for (int kk = 0; kk < 4; kk++) {
            float h = (kk == 0) ? hv.x : (kk == 1) ? hv.y : (kk == 2) ? hv.z : hv.w;
            unsigned long long h2;
            asm("mov.b64 %0, {%1, %1};" : "=l"(h2) : "f"(h));   // (h, h)
            int k = k4 * 4 + kk;
            #pragma unroll
            for (int j = 0; j < F4; j++) {
                float4 w = Ws[k * F4 + j];       // warp-uniform smem broadcast
                unsigned long long w01, w23;
                asm("mov.b64 %0, {%1, %2};" : "=l"(w01) : "f"(w.x), "f"(w.y));
                asm("mov.b64 %0, {%1, %2};" : "=l"(w23) : "f"(w.z), "f"(w.w));
                asm("fma.rn.f32x2 %0, %1, %2, %0;"
                    : "+l"(acc[2 * j + 0]) : "l"(h2), "l"(w01));
                asm("fma.rn.f32x2 %0, %1, %2, %0;"
                    : "+l"(acc[2 * j + 1]) : "l"(h2), "l"(w23));
            }
        }
    }

    float4* orow = reinterpret_cast<float4*>(out + (long)row * F);
    #pragma unroll
    for (int j = 0; j < F4; j++) {
        float x, y, z, w;
        asm("mov.b64 {%0, %1}, %2;" : "=f"(x), "=f"(y) : "l"(acc[2 * j + 0]));
        asm("mov.b64 {%0, %1}, %2;" : "=f"(z), "=f"(w) : "l"(acc[2 * j + 1]));
        orow[j] = make_float4(x, y, z, w);
    }
}

// ---------------------------------------------------------------------------
extern "C" void kernel_launch(void* const* d_in, const int* in_sizes, int n_in,
                              void* d_out, int out_size) {
    const float* feature = (const float*)d_in[0];
    const float* degree  = (const float*)d_in[1];
    const int*   src     = (const int*)d_in[2];
    const int*   dst     = (const int*)d_in[3];
    const float* W       = (const float*)d_in[4];
    const float* b       = (const float*)d_in[5];
    float*       out     = (float*)d_out;

    int N = in_sizes[1];
    int E = in_sizes[2];
    int nb = (N + SCAN_B - 1) / SCAN_B;

    scan1_kernel<<<nb, SCAN_B>>>(degree, N);
    scan2_kernel<<<1, MAX_SCAN_BLOCKS>>>(nb);
    scan3_kernel<<<nb, SCAN_B>>>(degree, N);

    int fthreads = (E > N * 8) ? E : N * 8;
    bucket_prescale_kernel<<<(fthreads + 255) / 256, 256>>>(
        feature, degree, src, dst, E, N);

    long long gthreads = (long long)N * 16;
    gather_kernel<<<(int)((gthreads + 255) / 256), 256>>>(degree, N);

    gemm_kernel<<<(N + 255) / 256, 256>>>(W, b, out, N);
}